// round 5
// baseline (speedup 1.0000x reference)
#include <cuda_runtime.h>
#include <cuda_bf16.h>
#include <math.h>

// Problem constants
#define BATCH 8
#define TLEN 4096
#define DDIM 1024
#define SDIM 128
#define CH   128            // chunk length
#define NCH  (TLEN / CH)    // 32 chunks per batch
#define MROWS (BATCH * TLEN) // 32768

// -------------------- packed f32x2 helpers (Blackwell FFMA2) --------------------
__device__ __forceinline__ unsigned long long pk2(float lo, float hi) {
    unsigned long long r;
    asm("mov.b64 %0, {%1, %2};" : "=l"(r) : "f"(lo), "f"(hi));
    return r;
}
__device__ __forceinline__ void upk2(unsigned long long v, float& lo, float& hi) {
    asm("mov.b64 {%0, %1}, %2;" : "=f"(lo), "=f"(hi) : "l"(v));
}
__device__ __forceinline__ unsigned long long fma2(unsigned long long a, unsigned long long b, unsigned long long c) {
    unsigned long long d;
    asm("fma.rn.f32x2 %0, %1, %2, %3;" : "=l"(d) : "l"(a), "l"(b), "l"(c));
    return d;
}
__device__ __forceinline__ unsigned long long mul2(unsigned long long a, unsigned long long b) {
    unsigned long long d;
    asm("mul.rn.f32x2 %0, %1, %2;" : "=l"(d) : "l"(a), "l"(b));
    return d;
}
__device__ __forceinline__ unsigned long long add2(unsigned long long a, unsigned long long b) {
    unsigned long long d;
    asm("add.rn.f32x2 %0, %1, %2;" : "=l"(d) : "l"(a), "l"(b));
    return d;
}

// -------------------- device scratch (no allocation allowed) --------------------
__device__ float g_Wcat[DDIM * 512];                 // packed [k][n], n = which*128+s (q,k,v,g)
__device__ float g_bcat[512];
__device__ float g_qkvg[(size_t)MROWS * 512];        // [m][512]: q|k|v|sigmoid(g)  (64 MB)
__device__ float g_states[(size_t)BATCH * NCH * SDIM * SDIM]; // [b][c][s][j] (16 MB)
__device__ float g_Dprod[BATCH * NCH * SDIM];        // per-chunk decay products
__device__ float g_attn[(size_t)MROWS * SDIM];       // recurrence outputs (16 MB)

// -------------------- K0: pack weights/biases --------------------
__global__ void pack_w_kernel(const float* __restrict__ Wq, const float* __restrict__ Wk,
                              const float* __restrict__ Wv, const float* __restrict__ Wg,
                              const float* __restrict__ bq, const float* __restrict__ bk,
                              const float* __restrict__ bv, const float* __restrict__ bg) {
    int idx = blockIdx.x * blockDim.x + threadIdx.x;
    if (idx < DDIM * 512) {
        int k = idx >> 9;
        int n = idx & 511;
        int which = n >> 7;
        int s = n & 127;
        const float* W = (which == 0) ? Wq : (which == 1) ? Wk : (which == 2) ? Wv : Wg;
        g_Wcat[idx] = W[k * SDIM + s];
    }
    if (idx < 512) {
        int which = idx >> 7, s = idx & 127;
        const float* bp = (which == 0) ? bq : (which == 1) ? bk : (which == 2) ? bv : bg;
        g_bcat[idx] = bp[s];
    }
}

// -------------------- K1: QKVG projection GEMM --------------------
// C[32768 x 512] = x[32768 x 1024] @ Wcat[1024 x 512], bias + sigmoid on g-block.
// BM=128, BN=128, BK=16, 256 threads, 8x8 microtile with packed FFMA2.
__global__ void __launch_bounds__(256, 2) gemm_qkvg_kernel(const float* __restrict__ x) {
    __shared__ float As[16][136];  // [k][m], padded
    __shared__ float Bs[16][128];  // [k][n]

    const int tid = threadIdx.x;
    const int tx = tid & 15;       // n subtile
    const int ty = tid >> 4;       // m subtile
    const int bm = blockIdx.x;
    const int bn = blockIdx.y;

    // load-index precompute (two float4 per thread per tile)
    const int fA0 = tid, fA1 = tid + 256;
    const int rA0 = fA0 >> 2, cA0 = (fA0 & 3) * 4;
    const int rA1 = fA1 >> 2, cA1 = (fA1 & 3) * 4;
    const int fB0 = tid, fB1 = tid + 256;
    const int kr0 = fB0 >> 5, cc0 = (fB0 & 31) * 4;
    const int kr1 = fB1 >> 5, cc1 = (fB1 & 31) * 4;

    const float* Ab = x + (size_t)bm * 128 * DDIM;
    const float* Bb = g_Wcat + bn * 128;

    float4 ra0 = *(const float4*)(Ab + (size_t)rA0 * DDIM + cA0);
    float4 ra1 = *(const float4*)(Ab + (size_t)rA1 * DDIM + cA1);
    float4 rb0 = *(const float4*)(Bb + (size_t)kr0 * 512 + cc0);
    float4 rb1 = *(const float4*)(Bb + (size_t)kr1 * 512 + cc1);

    As[cA0 + 0][rA0] = ra0.x; As[cA0 + 1][rA0] = ra0.y; As[cA0 + 2][rA0] = ra0.z; As[cA0 + 3][rA0] = ra0.w;
    As[cA1 + 0][rA1] = ra1.x; As[cA1 + 1][rA1] = ra1.y; As[cA1 + 2][rA1] = ra1.z; As[cA1 + 3][rA1] = ra1.w;
    *(float4*)&Bs[kr0][cc0] = rb0;
    *(float4*)&Bs[kr1][cc1] = rb1;
    __syncthreads();

    unsigned long long acc[8][4];
    #pragma unroll
    for (int i = 0; i < 8; i++)
        #pragma unroll
        for (int j = 0; j < 4; j++) acc[i][j] = 0ull;

    const int KITERS = DDIM / 16;
    for (int kt = 0; kt < KITERS; kt++) {
        if (kt + 1 < KITERS) {
            int ko = (kt + 1) * 16;
            ra0 = *(const float4*)(Ab + (size_t)rA0 * DDIM + ko + cA0);
            ra1 = *(const float4*)(Ab + (size_t)rA1 * DDIM + ko + cA1);
            rb0 = *(const float4*)(Bb + (size_t)(ko + kr0) * 512 + cc0);
            rb1 = *(const float4*)(Bb + (size_t)(ko + kr1) * 512 + cc1);
        }
        #pragma unroll
        for (int k = 0; k < 16; k++) {
            float4 a0 = *(const float4*)&As[k][ty * 8];
            float4 a1 = *(const float4*)&As[k][ty * 8 + 4];
            float4 b0 = *(const float4*)&Bs[k][tx * 8];
            float4 b1 = *(const float4*)&Bs[k][tx * 8 + 4];
            unsigned long long bp0 = pk2(b0.x, b0.y);
            unsigned long long bp1 = pk2(b0.z, b0.w);
            unsigned long long bp2 = pk2(b1.x, b1.y);
            unsigned long long bp3 = pk2(b1.z, b1.w);
            float av[8] = {a0.x, a0.y, a0.z, a0.w, a1.x, a1.y, a1.z, a1.w};
            #pragma unroll
            for (int i = 0; i < 8; i++) {
                unsigned long long ad = pk2(av[i], av[i]);
                acc[i][0] = fma2(ad, bp0, acc[i][0]);
                acc[i][1] = fma2(ad, bp1, acc[i][1]);
                acc[i][2] = fma2(ad, bp2, acc[i][2]);
                acc[i][3] = fma2(ad, bp3, acc[i][3]);
            }
        }
        __syncthreads();
        if (kt + 1 < KITERS) {
            As[cA0 + 0][rA0] = ra0.x; As[cA0 + 1][rA0] = ra0.y; As[cA0 + 2][rA0] = ra0.z; As[cA0 + 3][rA0] = ra0.w;
            As[cA1 + 0][rA1] = ra1.x; As[cA1 + 1][rA1] = ra1.y; As[cA1 + 2][rA1] = ra1.z; As[cA1 + 3][rA1] = ra1.w;
            *(float4*)&Bs[kr0][cc0] = rb0;
            *(float4*)&Bs[kr1][cc1] = rb1;
        }
        __syncthreads();
    }

    // epilogue: bias, sigmoid on g-block (bn == 3), write to g_qkvg
    const bool is_g = (bn == 3);
    const int m0 = bm * 128 + ty * 8;
    const int n0 = bn * 128 + tx * 8;
    #pragma unroll
    for (int i = 0; i < 8; i++) {
        float* orow = g_qkvg + (size_t)(m0 + i) * 512 + n0;
        #pragma unroll
        for (int jp = 0; jp < 4; jp++) {
            float lo, hi;
            upk2(acc[i][jp], lo, hi);
            lo += g_bcat[n0 + 2 * jp];
            hi += g_bcat[n0 + 2 * jp + 1];
            if (is_g) {
                lo = 1.0f / (1.0f + expf(-lo));
                hi = 1.0f / (1.0f + expf(-hi));
            }
            orow[2 * jp]     = lo;
            orow[2 * jp + 1] = hi;
        }
    }
}

// -------------------- K2: per-chunk local state (starting from zero) --------------------
// grid (NCH, BATCH), 256 threads. Thread (j = tid&127, half = tid>>7) owns state[sbase..sbase+63][j].
__global__ void __launch_bounds__(256, 2) chunk_local_kernel() {
    const int c = blockIdx.x, b = blockIdx.y;
    const int tid = threadIdx.x;
    const int j = tid & 127;
    const int half = tid >> 7;
    const int sb = half * 64;

    __shared__ __align__(16) float buf[2][512];
    const float* base = g_qkvg + (size_t)(b * TLEN + c * CH) * 512;

    ((float2*)buf[0])[tid] = ((const float2*)base)[tid];
    __syncthreads();

    unsigned long long st2[32];
    #pragma unroll
    for (int i = 0; i < 32; i++) st2[i] = 0ull;

    for (int t = 0; t < CH; t++) {
        const float* cur = buf[t & 1];
        if (t + 1 < CH)
            ((float2*)buf[(t + 1) & 1])[tid] = ((const float2*)(base + (size_t)(t + 1) * 512))[tid];

        float vj = cur[256 + j];
        unsigned long long vd = pk2(vj, vj);
        #pragma unroll
        for (int sq = 0; sq < 16; sq++) {
            int s = sb + sq * 4;
            ulonglong2 g4 = *(const ulonglong2*)&cur[384 + s];
            ulonglong2 k4 = *(const ulonglong2*)&cur[128 + s];
            st2[2 * sq]     = fma2(g4.x, st2[2 * sq],     mul2(k4.x, vd));
            st2[2 * sq + 1] = fma2(g4.y, st2[2 * sq + 1], mul2(k4.y, vd));
        }
        __syncthreads();
    }

    // write chunk-local state: g_states[b][c][s][j]
    float* out = g_states + ((size_t)(b * NCH + c) * SDIM + sb) * SDIM + j;
    #pragma unroll
    for (int sp = 0; sp < 32; sp++) {
        float lo, hi;
        upk2(st2[sp], lo, hi);
        out[(size_t)(2 * sp) * SDIM]     = lo;
        out[(size_t)(2 * sp + 1) * SDIM] = hi;
    }
}

// -------------------- K2b: per-chunk decay products --------------------
__global__ void chunk_decay_kernel() {
    const int c = blockIdx.x, b = blockIdx.y;
    const int s = threadIdx.x;  // 128 threads
    const float* gp = g_qkvg + (size_t)(b * TLEN + c * CH) * 512 + 384 + s;
    float p0 = 1.f, p1 = 1.f, p2 = 1.f, p3 = 1.f;
    for (int t = 0; t < CH; t += 4) {
        p0 *= gp[(size_t)(t + 0) * 512];
        p1 *= gp[(size_t)(t + 1) * 512];
        p2 *= gp[(size_t)(t + 2) * 512];
        p3 *= gp[(size_t)(t + 3) * 512];
    }
    g_Dprod[(b * NCH + c) * SDIM + s] = (p0 * p1) * (p2 * p3);
}

// -------------------- K3: sequential scan over chunks (in-place) --------------------
// After: g_states[b][c] holds the state at the START of chunk c.
__global__ void scan_states_kernel() {
    const int b = blockIdx.y;
    const int pos = blockIdx.x * 256 + threadIdx.x;  // 0..16383
    const int s = pos >> 7, j = pos & 127;
    float run = 0.f;
    for (int c = 0; c < NCH; c++) {
        size_t off = ((size_t)(b * NCH + c) * SDIM + s) * SDIM + j;
        float local = g_states[off];
        g_states[off] = run;
        run = g_Dprod[(b * NCH + c) * SDIM + s] * run + local;
    }
}

// -------------------- K4: chunk replay with outputs --------------------
__global__ void __launch_bounds__(256, 2) chunk_out_kernel() {
    const int c = blockIdx.x, b = blockIdx.y;
    const int tid = threadIdx.x;
    const int j = tid & 127;
    const int half = tid >> 7;
    const int sb = half * 64;

    __shared__ __align__(16) float buf[2][512];
    __shared__ float po[128];

    const float* base = g_qkvg + (size_t)(b * TLEN + c * CH) * 512;
    float* aout = g_attn + (size_t)(b * TLEN + c * CH) * SDIM;

    // load chunk-initial state
    const float* sin = g_states + ((size_t)(b * NCH + c) * SDIM + sb) * SDIM + j;
    unsigned long long st2[32];
    #pragma unroll
    for (int sp = 0; sp < 32; sp++)
        st2[sp] = pk2(sin[(size_t)(2 * sp) * SDIM], sin[(size_t)(2 * sp + 1) * SDIM]);

    ((float2*)buf[0])[tid] = ((const float2*)base)[tid];
    __syncthreads();

    for (int t = 0; t < CH; t++) {
        const float* cur = buf[t & 1];
        if (t + 1 < CH)
            ((float2*)buf[(t + 1) & 1])[tid] = ((const float2*)(base + (size_t)(t + 1) * 512))[tid];

        float vj = cur[256 + j];
        unsigned long long vd = pk2(vj, vj);
        unsigned long long accA = 0ull, accB = 0ull;
        #pragma unroll
        for (int sq = 0; sq < 16; sq++) {
            int s = sb + sq * 4;
            ulonglong2 g4 = *(const ulonglong2*)&cur[384 + s];
            ulonglong2 k4 = *(const ulonglong2*)&cur[128 + s];
            ulonglong2 q4 = *(const ulonglong2*)&cur[s];
            st2[2 * sq]     = fma2(g4.x, st2[2 * sq],     mul2(k4.x, vd));
            st2[2 * sq + 1] = fma2(g4.y, st2[2 * sq + 1], mul2(k4.y, vd));
            accA = fma2(q4.x, st2[2 * sq],     accA);
            accB = fma2(q4.y, st2[2 * sq + 1], accB);
        }
        unsigned long long accT = add2(accA, accB);
        float lo, hi;
        upk2(accT, lo, hi);
        float part = lo + hi;

        if (half == 0) po[j] = part;
        __syncthreads();
        if (half == 1) aout[(size_t)t * SDIM + j] = part + po[j];
        __syncthreads();
    }
}

// -------------------- K5: output GEMM + residual --------------------
// y[32768 x 1024] = attn[32768 x 128] @ Wo[128 x 1024] + bo + x  -> written to d_out
__global__ void __launch_bounds__(256, 2) gemm_out_kernel(const float* __restrict__ x,
                                                          const float* __restrict__ Wo,
                                                          const float* __restrict__ bo,
                                                          float* __restrict__ y) {
    __shared__ float As[16][136];
    __shared__ float Bs[16][128];

    const int tid = threadIdx.x;
    const int tx = tid & 15;
    const int ty = tid >> 4;
    const int bm = blockIdx.x;
    const int bn = blockIdx.y;

    const int fA0 = tid, fA1 = tid + 256;
    const int rA0 = fA0 >> 2, cA0 = (fA0 & 3) * 4;
    const int rA1 = fA1 >> 2, cA1 = (fA1 & 3) * 4;
    const int fB0 = tid, fB1 = tid + 256;
    const int kr0 = fB0 >> 5, cc0 = (fB0 & 31) * 4;
    const int kr1 = fB1 >> 5, cc1 = (fB1 & 31) * 4;

    const float* Ab = g_attn + (size_t)bm * 128 * SDIM;
    const float* Bb = Wo + bn * 128;

    float4 ra0 = *(const float4*)(Ab + (size_t)rA0 * SDIM + cA0);
    float4 ra1 = *(const float4*)(Ab + (size_t)rA1 * SDIM + cA1);
    float4 rb0 = *(const float4*)(Bb + (size_t)kr0 * DDIM + cc0);
    float4 rb1 = *(const float4*)(Bb + (size_t)kr1 * DDIM + cc1);

    As[cA0 + 0][rA0] = ra0.x; As[cA0 + 1][rA0] = ra0.y; As[cA0 + 2][rA0] = ra0.z; As[cA0 + 3][rA0] = ra0.w;
    As[cA1 + 0][rA1] = ra1.x; As[cA1 + 1][rA1] = ra1.y; As[cA1 + 2][rA1] = ra1.z; As[cA1 + 3][rA1] = ra1.w;
    *(float4*)&Bs[kr0][cc0] = rb0;
    *(float4*)&Bs[kr1][cc1] = rb1;
    __syncthreads();

    unsigned long long acc[8][4];
    #pragma unroll
    for (int i = 0; i < 8; i++)
        #pragma unroll
        for (int jj = 0; jj < 4; jj++) acc[i][jj] = 0ull;

    const int KITERS = SDIM / 16;  // 8
    for (int kt = 0; kt < KITERS; kt++) {
        if (kt + 1 < KITERS) {
            int ko = (kt + 1) * 16;
            ra0 = *(const float4*)(Ab + (size_t)rA0 * SDIM + ko + cA0);
            ra1 = *(const float4*)(Ab + (size_t)rA1 * SDIM + ko + cA1);
            rb0 = *(const float4*)(Bb + (size_t)(ko + kr0) * DDIM + cc0);
            rb1 = *(const float4*)(Bb + (size_t)(ko + kr1) * DDIM + cc1);
        }
        #pragma unroll
        for (int k = 0; k < 16; k++) {
            float4 a0 = *(const float4*)&As[k][ty * 8];
            float4 a1 = *(const float4*)&As[k][ty * 8 + 4];
            float4 b0 = *(const float4*)&Bs[k][tx * 8];
            float4 b1 = *(const float4*)&Bs[k][tx * 8 + 4];
            unsigned long long bp0 = pk2(b0.x, b0.y);
            unsigned long long bp1 = pk2(b0.z, b0.w);
            unsigned long long bp2 = pk2(b1.x, b1.y);
            unsigned long long bp3 = pk2(b1.z, b1.w);
            float av[8] = {a0.x, a0.y, a0.z, a0.w, a1.x, a1.y, a1.z, a1.w};
            #pragma unroll
            for (int i = 0; i < 8; i++) {
                unsigned long long ad = pk2(av[i], av[i]);
                acc[i][0] = fma2(ad, bp0, acc[i][0]);
                acc[i][1] = fma2(ad, bp1, acc[i][1]);
                acc[i][2] = fma2(ad, bp2, acc[i][2]);
                acc[i][3] = fma2(ad, bp3, acc[i][3]);
            }
        }
        __syncthreads();
        if (kt + 1 < KITERS) {
            As[cA0 + 0][rA0] = ra0.x; As[cA0 + 1][rA0] = ra0.y; As[cA0 + 2][rA0] = ra0.z; As[cA0 + 3][rA0] = ra0.w;
            As[cA1 + 0][rA1] = ra1.x; As[cA1 + 1][rA1] = ra1.y; As[cA1 + 2][rA1] = ra1.z; As[cA1 + 3][rA1] = ra1.w;
            *(float4*)&Bs[kr0][cc0] = rb0;
            *(float4*)&Bs[kr1][cc1] = rb1;
        }
        __syncthreads();
    }

    const int m0 = bm * 128 + ty * 8;
    const int n0 = bn * 128 + tx * 8;
    #pragma unroll
    for (int i = 0; i < 8; i++) {
        const float* xrow = x + (size_t)(m0 + i) * DDIM + n0;
        float* yrow = y + (size_t)(m0 + i) * DDIM + n0;
        #pragma unroll
        for (int jp = 0; jp < 4; jp++) {
            float lo, hi;
            upk2(acc[i][jp], lo, hi);
            yrow[2 * jp]     = lo + bo[n0 + 2 * jp]     + xrow[2 * jp];
            yrow[2 * jp + 1] = hi + bo[n0 + 2 * jp + 1] + xrow[2 * jp + 1];
        }
    }
}

// -------------------- K6: LayerNorm in place on d_out --------------------
__global__ void ln_kernel(const float* __restrict__ gamma, const float* __restrict__ beta,
                          float* __restrict__ y) {
    const int row = blockIdx.x;
    const int tid = threadIdx.x;  // 256
    float4 v = ((float4*)y)[(size_t)row * 256 + tid];
    float s  = v.x + v.y + v.z + v.w;
    float sq = v.x * v.x + v.y * v.y + v.z * v.z + v.w * v.w;
    #pragma unroll
    for (int o = 16; o; o >>= 1) {
        s  += __shfl_xor_sync(0xffffffffu, s, o);
        sq += __shfl_xor_sync(0xffffffffu, sq, o);
    }
    __shared__ float ws[8], wq[8];
    int w = tid >> 5, l = tid & 31;
    if (l == 0) { ws[w] = s; wq[w] = sq; }
    __syncthreads();
    if (tid < 32) {
        s  = (tid < 8) ? ws[tid] : 0.f;
        sq = (tid < 8) ? wq[tid] : 0.f;
        #pragma unroll
        for (int o = 4; o; o >>= 1) {
            s  += __shfl_xor_sync(0xffffffffu, s, o);
            sq += __shfl_xor_sync(0xffffffffu, sq, o);
        }
        if (tid == 0) { ws[0] = s; wq[0] = sq; }
    }
    __syncthreads();
    const float mu = ws[0] * (1.0f / 1024.0f);
    const float var = wq[0] * (1.0f / 1024.0f) - mu * mu;
    const float rs = rsqrtf(var + 1e-5f);
    const int n = tid * 4;
    v.x = (v.x - mu) * rs * gamma[n + 0] + beta[n + 0];
    v.y = (v.y - mu) * rs * gamma[n + 1] + beta[n + 1];
    v.z = (v.z - mu) * rs * gamma[n + 2] + beta[n + 2];
    v.w = (v.w - mu) * rs * gamma[n + 3] + beta[n + 3];
    ((float4*)y)[(size_t)row * 256 + tid] = v;
}

// -------------------- launch --------------------
extern "C" void kernel_launch(void* const* d_in, const int* in_sizes, int n_in,
                              void* d_out, int out_size) {
    const float* x     = (const float*)d_in[0];
    const float* Wq    = (const float*)d_in[1];
    const float* bq    = (const float*)d_in[2];
    const float* Wk    = (const float*)d_in[3];
    const float* bk    = (const float*)d_in[4];
    const float* Wv    = (const float*)d_in[5];
    const float* bv    = (const float*)d_in[6];
    const float* Wg    = (const float*)d_in[7];
    const float* bg    = (const float*)d_in[8];
    const float* Wo    = (const float*)d_in[9];
    const float* bo    = (const float*)d_in[10];
    const float* gamma = (const float*)d_in[11];
    const float* beta  = (const float*)d_in[12];
    float* out = (float*)d_out;

    pack_w_kernel<<<(DDIM * 512 + 255) / 256, 256>>>(Wq, Wk, Wv, Wg, bq, bk, bv, bg);
    gemm_qkvg_kernel<<<dim3(MROWS / 128, 4), 256>>>(x);
    chunk_local_kernel<<<dim3(NCH, BATCH), 256>>>();
    chunk_decay_kernel<<<dim3(NCH, BATCH), 128>>>();
    scan_states_kernel<<<dim3(SDIM * SDIM / 256, BATCH), 256>>>();
    chunk_out_kernel<<<dim3(NCH, BATCH), 256>>>();
    gemm_out_kernel<<<dim3(MROWS / 128, DDIM / 128), 256>>>(x, Wo, bo, out);
    ln_kernel<<<MROWS, 256>>>(gamma, beta, out);
}